// round 1
// baseline (speedup 1.0000x reference)
#include <cuda_runtime.h>
#include <cuda_bf16.h>

#define NN 50000
#define NE 640000
#define RK 128
#define NG 50
#define LN_EPS 1e-5f

// ---------------- scratch (static device globals; no allocation allowed) ----
__device__ float g_h[NN * RK];      // post-GEMM, pre-aggregation features
__device__ float g_bufA[NN * RK];   // ping
__device__ float g_bufB[NN * RK];   // pong
__device__ int   g_deg_in[NN];
__device__ int   g_deg_out[NN];
__device__ float g_inv_in[NN];
__device__ float g_inv_out[NN];
__device__ int   g_off[NN + 1];     // CSR offsets by dst
__device__ int   g_cur[NN];         // fill cursors
__device__ int   g_esrc[NE];        // src ids bucketed by dst

// ---------------- f32x2 packed-FMA helpers (sm_103a) ------------------------
__device__ __forceinline__ unsigned long long pack2_dup(float x) {
    unsigned long long r;
    unsigned int u = __float_as_uint(x);
    asm("mov.b64 %0, {%1, %1};" : "=l"(r) : "r"(u));
    return r;
}
__device__ __forceinline__ unsigned long long fma2(unsigned long long a,
                                                   unsigned long long b,
                                                   unsigned long long c) {
    unsigned long long d;
    asm("fma.rn.f32x2 %0, %1, %2, %3;" : "=l"(d) : "l"(a), "l"(b), "l"(c));
    return d;
}
__device__ __forceinline__ void unpack2(unsigned long long v, float& a, float& b) {
    unsigned int lo, hi;
    asm("mov.b64 {%0, %1}, %2;" : "=r"(lo), "=r"(hi) : "l"(v));
    a = __uint_as_float(lo);
    b = __uint_as_float(hi);
}

// ---------------- prep kernels ----------------------------------------------
__global__ void zero_deg_kernel() {
    int i = blockIdx.x * blockDim.x + threadIdx.x;
    if (i < NN) { g_deg_in[i] = 0; g_deg_out[i] = 0; }
}

__global__ void degree_kernel(const int* __restrict__ src, const int* __restrict__ dst) {
    int i = blockIdx.x * blockDim.x + threadIdx.x;
    if (i < NE) {
        atomicAdd(&g_deg_out[src[i]], 1);
        atomicAdd(&g_deg_in[dst[i]], 1);
    }
}

__global__ void invsqrt_kernel() {
    int i = blockIdx.x * blockDim.x + threadIdx.x;
    if (i < NN) {
        g_inv_out[i] = rsqrtf(fmaxf((float)g_deg_out[i], 1.0f));
        g_inv_in[i]  = rsqrtf(fmaxf((float)g_deg_in[i], 1.0f));
    }
}

// Single-block exclusive scan of deg_in -> offsets (+ cursor copy).
__global__ void scan_kernel() {
    __shared__ int wsum[32];
    __shared__ int carry;
    int tid = threadIdx.x, lane = tid & 31, wid = tid >> 5;
    if (tid == 0) carry = 0;
    __syncthreads();
    for (int base = 0; base < NN; base += 1024) {
        int i = base + tid;
        int v = (i < NN) ? g_deg_in[i] : 0;
        int x = v;
        #pragma unroll
        for (int o = 1; o < 32; o <<= 1) {
            int t = __shfl_up_sync(0xffffffffu, x, o);
            if (lane >= o) x += t;
        }
        if (lane == 31) wsum[wid] = x;
        __syncthreads();
        if (wid == 0) {
            int y = wsum[lane];
            #pragma unroll
            for (int o = 1; o < 32; o <<= 1) {
                int t = __shfl_up_sync(0xffffffffu, y, o);
                if (lane >= o) y += t;
            }
            wsum[lane] = y;
        }
        __syncthreads();
        int wpref = wid ? wsum[wid - 1] : 0;
        int incl = x + wpref;
        int excl = incl - v;
        int c = carry;
        if (i < NN) {
            g_off[i] = c + excl;
            g_cur[i] = c + excl;
        }
        __syncthreads();
        if (tid == 1023) carry = c + incl;
        __syncthreads();
    }
    if (threadIdx.x == 0) g_off[NN] = carry;
}

__global__ void bucket_fill_kernel(const int* __restrict__ src, const int* __restrict__ dst) {
    int i = blockIdx.x * blockDim.x + threadIdx.x;
    if (i < NE) {
        int d = dst[i];
        int p = atomicAdd(&g_cur[d], 1);
        g_esrc[p] = src[i];
    }
}

// ---------------- GEMM: h = (X @ W) * inv_sqrt_out --------------------------
// Block: 64 rows, 256 threads. W (128x128) fully in smem; X tile in smem
// (row-major, stride 129). Thread computes 4 rows x 8 cols via packed f32x2 FMA.
#define GEMM_BM 64
#define ASH_STRIDE 129
#define GEMM_SMEM_BYTES ((RK * RK + GEMM_BM * ASH_STRIDE) * 4)

__global__ void __launch_bounds__(256, 2)
gemm_kernel(const float* __restrict__ Xext, const float* __restrict__ W, int sel) {
    const float* X = (sel == 0) ? Xext : ((sel == 1) ? g_bufA : g_bufB);
    extern __shared__ float sm[];
    float* Wsh = sm;                 // 128*128
    float* Ash = sm + RK * RK;       // 64 * 129
    const int tid = threadIdx.x;
    const int rowBase = blockIdx.x * GEMM_BM;

    // Load W (16384 floats = 4096 float4)
    {
        const float4* Wg = (const float4*)W;
        float4* Ws4 = (float4*)Wsh;
        #pragma unroll
        for (int j = 0; j < 16; j++) Ws4[tid + j * 256] = Wg[tid + j * 256];
    }
    // Load X tile (64x128), row-major padded stride 129
    #pragma unroll
    for (int j = 0; j < 8; j++) {
        int idx = tid + j * 256;
        int row = idx >> 5;       // 0..63 (constant per warp -> coalesced gmem)
        int kq  = idx & 31;       // 0..31
        float4 v = make_float4(0.f, 0.f, 0.f, 0.f);
        int grow = rowBase + row;
        if (grow < NN) v = *(const float4*)(X + grow * RK + kq * 4);
        float* p = Ash + row * ASH_STRIDE + kq * 4;
        p[0] = v.x; p[1] = v.y; p[2] = v.z; p[3] = v.w;
    }
    __syncthreads();

    const int tr = tid >> 4;   // 0..15 -> rows tr*4 .. tr*4+3
    const int tc = tid & 15;   // cols tc*8 .. tc*8+7
    unsigned long long acc[4][4];
    #pragma unroll
    for (int r = 0; r < 4; r++)
        #pragma unroll
        for (int p = 0; p < 4; p++) acc[r][p] = 0ULL;

    const float* a0 = Ash + (tr * 4 + 0) * ASH_STRIDE;
    const float* a1 = Ash + (tr * 4 + 1) * ASH_STRIDE;
    const float* a2 = Ash + (tr * 4 + 2) * ASH_STRIDE;
    const float* a3 = Ash + (tr * 4 + 3) * ASH_STRIDE;
    const float* wbase = Wsh + tc * 8;

    #pragma unroll 4
    for (int k = 0; k < RK; k++) {
        ulonglong2 wA = *(const ulonglong2*)(wbase + k * RK);
        ulonglong2 wB = *(const ulonglong2*)(wbase + k * RK + 4);
        unsigned long long av0 = pack2_dup(a0[k]);
        unsigned long long av1 = pack2_dup(a1[k]);
        unsigned long long av2 = pack2_dup(a2[k]);
        unsigned long long av3 = pack2_dup(a3[k]);
        acc[0][0] = fma2(av0, wA.x, acc[0][0]);
        acc[0][1] = fma2(av0, wA.y, acc[0][1]);
        acc[0][2] = fma2(av0, wB.x, acc[0][2]);
        acc[0][3] = fma2(av0, wB.y, acc[0][3]);
        acc[1][0] = fma2(av1, wA.x, acc[1][0]);
        acc[1][1] = fma2(av1, wA.y, acc[1][1]);
        acc[1][2] = fma2(av1, wB.x, acc[1][2]);
        acc[1][3] = fma2(av1, wB.y, acc[1][3]);
        acc[2][0] = fma2(av2, wA.x, acc[2][0]);
        acc[2][1] = fma2(av2, wA.y, acc[2][1]);
        acc[2][2] = fma2(av2, wB.x, acc[2][2]);
        acc[2][3] = fma2(av2, wB.y, acc[2][3]);
        acc[3][0] = fma2(av3, wA.x, acc[3][0]);
        acc[3][1] = fma2(av3, wA.y, acc[3][1]);
        acc[3][2] = fma2(av3, wB.x, acc[3][2]);
        acc[3][3] = fma2(av3, wB.y, acc[3][3]);
    }

    #pragma unroll
    for (int r = 0; r < 4; r++) {
        int grow = rowBase + tr * 4 + r;
        if (grow < NN) {
            float s = g_inv_out[grow];
            float x0, x1, x2, x3, x4, x5, x6, x7;
            unpack2(acc[r][0], x0, x1);
            unpack2(acc[r][1], x2, x3);
            unpack2(acc[r][2], x4, x5);
            unpack2(acc[r][3], x6, x7);
            float4 o0 = make_float4(x0 * s, x1 * s, x2 * s, x3 * s);
            float4 o1 = make_float4(x4 * s, x5 * s, x6 * s, x7 * s);
            *(float4*)(g_h + grow * RK + tc * 8)     = o0;
            *(float4*)(g_h + grow * RK + tc * 8 + 4) = o1;
        }
    }
}

// ---------------- aggregation + bias + LayerNorm + ReLU ---------------------
// One warp per dst node; each lane owns 4 contiguous floats (float4).
__global__ void __launch_bounds__(256)
agg_ln_kernel(const float* __restrict__ b, const float* __restrict__ gamma,
              const float* __restrict__ beta, int sel) {
    int warp = (blockIdx.x * blockDim.x + threadIdx.x) >> 5;
    int lane = threadIdx.x & 31;
    if (warp >= NN) return;
    float* O = (sel == 1) ? g_bufB : g_bufA;

    int start = g_off[warp];
    int end   = g_off[warp + 1];
    const float4* H4 = (const float4*)g_h;

    float ax = 0.f, ay = 0.f, az = 0.f, aw = 0.f;
    for (int eb = start; eb < end; eb += 32) {
        int cnt = min(32, end - eb);
        int se = (lane < cnt) ? g_esrc[eb + lane] : 0;
        for (int j = 0; j < cnt; j++) {
            int s = __shfl_sync(0xffffffffu, se, j);
            float4 v = H4[s * 32 + lane];
            ax += v.x; ay += v.y; az += v.z; aw += v.w;
        }
    }

    float inv = g_inv_in[warp];
    float4 bb = ((const float4*)b)[lane];
    float vx = ax * inv + bb.x;
    float vy = ay * inv + bb.y;
    float vz = az * inv + bb.z;
    float vw = aw * inv + bb.w;

    float sum = vx + vy + vz + vw;
    #pragma unroll
    for (int o = 16; o; o >>= 1) sum += __shfl_xor_sync(0xffffffffu, sum, o);
    float mean = sum * (1.0f / 128.0f);

    float cx = vx - mean, cy = vy - mean, cz = vz - mean, cw = vw - mean;
    float ss = cx * cx + cy * cy + cz * cz + cw * cw;
    #pragma unroll
    for (int o = 16; o; o >>= 1) ss += __shfl_xor_sync(0xffffffffu, ss, o);
    float rstd = rsqrtf(ss * (1.0f / 128.0f) + LN_EPS);

    float4 gm = ((const float4*)gamma)[lane];
    float4 bt = ((const float4*)beta)[lane];
    float4 o4;
    o4.x = fmaxf(cx * rstd * gm.x + bt.x, 0.f);
    o4.y = fmaxf(cy * rstd * gm.y + bt.y, 0.f);
    o4.z = fmaxf(cz * rstd * gm.z + bt.z, 0.f);
    o4.w = fmaxf(cw * rstd * gm.w + bt.w, 0.f);
    ((float4*)O)[warp * 32 + lane] = o4;
}

// ---------------- readout ---------------------------------------------------
__global__ void out_kernel(const int* __restrict__ bnn, float* __restrict__ out) {
    int g = blockIdx.x;
    int t = threadIdx.x;
    int base = 0;
    for (int i = 0; i < g; i++) base += bnn[i];
    out[g * RK + t] = g_bufA[base * RK + t];
}

// ---------------- launch ----------------------------------------------------
extern "C" void kernel_launch(void* const* d_in, const int* in_sizes, int n_in,
                              void* d_out, int out_size) {
    const float* features = (const float*)d_in[0];
    const int*   src      = (const int*)d_in[1];
    const int*   dst      = (const int*)d_in[2];
    const int*   bnn      = (const int*)d_in[3];
    const float* Ws       = (const float*)d_in[4];
    const float* bs       = (const float*)d_in[5];
    const float* gammas   = (const float*)d_in[6];
    const float* betas    = (const float*)d_in[7];
    float* out = (float*)d_out;

    cudaFuncSetAttribute(gemm_kernel, cudaFuncAttributeMaxDynamicSharedMemorySize,
                         GEMM_SMEM_BYTES);

    zero_deg_kernel<<<(NN + 255) / 256, 256>>>();
    degree_kernel<<<(NE + 255) / 256, 256>>>(src, dst);
    invsqrt_kernel<<<(NN + 255) / 256, 256>>>();
    scan_kernel<<<1, 1024>>>();
    bucket_fill_kernel<<<(NE + 255) / 256, 256>>>(src, dst);

    const int gemm_blocks = (NN + GEMM_BM - 1) / GEMM_BM;
    const int agg_blocks = (NN * 32 + 255) / 256;
    for (int i = 0; i < 3; i++) {
        gemm_kernel<<<gemm_blocks, 256, GEMM_SMEM_BYTES>>>(features, Ws + i * RK * RK, i);
        agg_ln_kernel<<<agg_blocks, 256>>>(bs + i * RK, gammas + i * RK, betas + i * RK, i);
    }
    out_kernel<<<NG, RK>>>(bnn, out);
}

// round 3
// speedup vs baseline: 1.9686x; 1.9686x over previous
#include <cuda_runtime.h>
#include <cuda_bf16.h>

#define NN 50000
#define NE 640000
#define RK 128
#define NG 50
#define LN_EPS 1e-5f
#define NB 49   // scan blocks: ceil(50000/1024)

// ---------------- scratch (static device globals) ---------------------------
__device__ float g_h[NN * RK];      // post-GEMM features (scaled by inv_out)
__device__ float g_bufA[NN * RK];   // feats1 (valid at N0 rows)
__device__ float g_bufB[NN * RK];   // feats2 (valid at N1 rows)
__device__ int   g_deg_in[NN];
__device__ int   g_deg_out[NN];
__device__ float g_inv_in[NN];
__device__ float g_inv_out[NN];
__device__ int   g_off[NN + 1];     // CSR offsets by dst
__device__ int   g_cur[NN];
__device__ int   g_esrc[NE];        // src ids bucketed by dst
__device__ int   g_bsum[64];
__device__ int   g_tgt[NG];
__device__ int   g_mark0[NN];
__device__ int   g_mark1[NN];
__device__ int   g_n0_list[NN];
__device__ int   g_n1_list[NN];
__device__ int   g_count0;
__device__ int   g_count1;

// ---------------- f32x2 packed-FMA helpers (sm_103a) ------------------------
__device__ __forceinline__ unsigned long long pack2_dup(float x) {
    unsigned long long r;
    unsigned int u = __float_as_uint(x);
    asm("mov.b64 %0, {%1, %1};" : "=l"(r) : "r"(u));
    return r;
}
__device__ __forceinline__ unsigned long long fma2(unsigned long long a,
                                                   unsigned long long b,
                                                   unsigned long long c) {
    unsigned long long d;
    asm("fma.rn.f32x2 %0, %1, %2, %3;" : "=l"(d) : "l"(a), "l"(b), "l"(c));
    return d;
}
__device__ __forceinline__ void unpack2(unsigned long long v, float& a, float& b) {
    unsigned int lo, hi;
    asm("mov.b64 {%0, %1}, %2;" : "=r"(lo), "=r"(hi) : "l"(v));
    a = __uint_as_float(lo);
    b = __uint_as_float(hi);
}

// ---------------- prep kernels ----------------------------------------------
__global__ void zero_kernel() {
    int i = blockIdx.x * blockDim.x + threadIdx.x;
    if (i < NN) { g_deg_in[i] = 0; g_deg_out[i] = 0; g_mark0[i] = 0; g_mark1[i] = 0; }
    if (i == 0) { g_count0 = 0; g_count1 = 0; }
}

__global__ void degree_kernel(const int* __restrict__ src, const int* __restrict__ dst) {
    int i = blockIdx.x * blockDim.x + threadIdx.x;
    if (i < NE) {
        atomicAdd(&g_deg_out[src[i]], 1);
        atomicAdd(&g_deg_in[dst[i]], 1);
    }
}

__global__ void invsqrt_kernel() {
    int i = blockIdx.x * blockDim.x + threadIdx.x;
    if (i < NN) {
        g_inv_out[i] = rsqrtf(fmaxf((float)g_deg_out[i], 1.0f));
        g_inv_in[i]  = rsqrtf(fmaxf((float)g_deg_in[i], 1.0f));
    }
}

// Hierarchical scan: per-block local exclusive scan + block totals.
__global__ void scan1_kernel() {
    __shared__ int wsum[32];
    int tid = threadIdx.x, lane = tid & 31, wid = tid >> 5;
    int i = blockIdx.x * 1024 + tid;
    int v = (i < NN) ? g_deg_in[i] : 0;
    int x = v;
    #pragma unroll
    for (int o = 1; o < 32; o <<= 1) {
        int t = __shfl_up_sync(0xffffffffu, x, o);
        if (lane >= o) x += t;
    }
    if (lane == 31) wsum[wid] = x;
    __syncthreads();
    if (wid == 0) {
        int y = wsum[lane];
        #pragma unroll
        for (int o = 1; o < 32; o <<= 1) {
            int t = __shfl_up_sync(0xffffffffu, y, o);
            if (lane >= o) y += t;
        }
        wsum[lane] = y;
    }
    __syncthreads();
    int wpref = wid ? wsum[wid - 1] : 0;
    int incl = x + wpref;
    if (i < NN) g_off[i] = incl - v;     // block-local exclusive
    if (tid == 1023) g_bsum[blockIdx.x] = incl;
}

__global__ void scan2_kernel() {   // 1 block, 64 threads
    __shared__ int s[64];
    int tid = threadIdx.x;
    s[tid] = (tid < NB) ? g_bsum[tid] : 0;
    __syncthreads();
    if (tid == 0) {
        int tot = 0;
        for (int i = 0; i < NB; i++) { int t = s[i]; s[i] = tot; tot += t; }
        g_off[NN] = tot;
    }
    __syncthreads();
    if (tid < NB) g_bsum[tid] = s[tid];
}

__global__ void scan3_kernel() {
    int i = blockIdx.x * 1024 + threadIdx.x;
    if (i < NN) {
        int o = g_off[i] + g_bsum[blockIdx.x];
        g_off[i] = o;
        g_cur[i] = o;
    }
}

__global__ void bucket_fill_kernel(const int* __restrict__ src, const int* __restrict__ dst) {
    int i = blockIdx.x * blockDim.x + threadIdx.x;
    if (i < NE) {
        int d = dst[i];
        int p = atomicAdd(&g_cur[d], 1);
        g_esrc[p] = src[i];
    }
}

// ---------------- frontier construction -------------------------------------
// Single block: compute targets from batch_num_nodes, then N1 = srcs of their in-edges.
__global__ void frontier1_kernel(const int* __restrict__ bnn) {
    __shared__ int sb[64];
    int tid = threadIdx.x, lane = tid & 31, wid = tid >> 5;
    if (tid < 64) sb[tid] = (tid < NG) ? bnn[tid] : 0;
    __syncthreads();
    if (tid == 0) {
        int base = 0;
        for (int i = 0; i < NG; i++) { g_tgt[i] = base; base += sb[i]; }
    }
    __syncthreads();
    for (int t = wid; t < NG; t += blockDim.x >> 5) {
        int node = g_tgt[t];
        int st = g_off[node], en = g_off[node + 1];
        for (int e = st + lane; e < en; e += 32) {
            int s = g_esrc[e];
            if (atomicExch(&g_mark1[s], 1) == 0) {
                int p = atomicAdd(&g_count1, 1);
                g_n1_list[p] = s;
            }
        }
    }
}

// N0 = srcs of in-edges of N1 (grid-stride over N1 entries).
__global__ void frontier0_kernel() {
    int lane = threadIdx.x & 31;
    int w = (blockIdx.x * blockDim.x + threadIdx.x) >> 5;
    int nw = (gridDim.x * blockDim.x) >> 5;
    int cnt = g_count1;
    for (int i = w; i < cnt; i += nw) {
        int node = g_n1_list[i];
        int st = g_off[node], en = g_off[node + 1];
        for (int e = st + lane; e < en; e += 32) {
            int s = g_esrc[e];
            if (atomicExch(&g_mark0[s], 1) == 0) {
                int p = atomicAdd(&g_count0, 1);
                g_n0_list[p] = s;
            }
        }
    }
}

// ---------------- GEMM (full, layer 0): g_h = (X @ W) * inv_out -------------
#define GEMM_BM 64
#define ASH_STRIDE 129
#define GEMM_SMEM_BYTES ((RK * RK + GEMM_BM * ASH_STRIDE) * 4)

__global__ void __launch_bounds__(256, 2)
gemm_full_kernel(const float* __restrict__ X, const float* __restrict__ W) {
    extern __shared__ float sm[];
    float* Wsh = sm;
    float* Ash = sm + RK * RK;
    const int tid = threadIdx.x;
    const int rowBase = blockIdx.x * GEMM_BM;

    {
        const float4* Wg = (const float4*)W;
        float4* Ws4 = (float4*)Wsh;
        #pragma unroll
        for (int j = 0; j < 16; j++) Ws4[tid + j * 256] = Wg[tid + j * 256];
    }
    #pragma unroll
    for (int j = 0; j < 8; j++) {
        int idx = tid + j * 256;
        int row = idx >> 5;
        int kq  = idx & 31;
        float4 v = make_float4(0.f, 0.f, 0.f, 0.f);
        int grow = rowBase + row;
        if (grow < NN) v = *(const float4*)(X + grow * RK + kq * 4);
        float* p = Ash + row * ASH_STRIDE + kq * 4;
        p[0] = v.x; p[1] = v.y; p[2] = v.z; p[3] = v.w;
    }
    __syncthreads();

    const int tr = tid >> 4;
    const int tc = tid & 15;
    unsigned long long acc[4][4];
    #pragma unroll
    for (int r = 0; r < 4; r++)
        #pragma unroll
        for (int p = 0; p < 4; p++) acc[r][p] = 0ULL;

    const float* a0 = Ash + (tr * 4 + 0) * ASH_STRIDE;
    const float* a1 = Ash + (tr * 4 + 1) * ASH_STRIDE;
    const float* a2 = Ash + (tr * 4 + 2) * ASH_STRIDE;
    const float* a3 = Ash + (tr * 4 + 3) * ASH_STRIDE;
    const float* wbase = Wsh + tc * 8;

    #pragma unroll 4
    for (int k = 0; k < RK; k++) {
        ulonglong2 wA = *(const ulonglong2*)(wbase + k * RK);
        ulonglong2 wB = *(const ulonglong2*)(wbase + k * RK + 4);
        unsigned long long av0 = pack2_dup(a0[k]);
        unsigned long long av1 = pack2_dup(a1[k]);
        unsigned long long av2 = pack2_dup(a2[k]);
        unsigned long long av3 = pack2_dup(a3[k]);
        acc[0][0] = fma2(av0, wA.x, acc[0][0]);
        acc[0][1] = fma2(av0, wA.y, acc[0][1]);
        acc[0][2] = fma2(av0, wB.x, acc[0][2]);
        acc[0][3] = fma2(av0, wB.y, acc[0][3]);
        acc[1][0] = fma2(av1, wA.x, acc[1][0]);
        acc[1][1] = fma2(av1, wA.y, acc[1][1]);
        acc[1][2] = fma2(av1, wB.x, acc[1][2]);
        acc[1][3] = fma2(av1, wB.y, acc[1][3]);
        acc[2][0] = fma2(av2, wA.x, acc[2][0]);
        acc[2][1] = fma2(av2, wA.y, acc[2][1]);
        acc[2][2] = fma2(av2, wB.x, acc[2][2]);
        acc[2][3] = fma2(av2, wB.y, acc[2][3]);
        acc[3][0] = fma2(av3, wA.x, acc[3][0]);
        acc[3][1] = fma2(av3, wA.y, acc[3][1]);
        acc[3][2] = fma2(av3, wB.x, acc[3][2]);
        acc[3][3] = fma2(av3, wB.y, acc[3][3]);
    }

    #pragma unroll
    for (int r = 0; r < 4; r++) {
        int grow = rowBase + tr * 4 + r;
        if (grow < NN) {
            float s = g_inv_out[grow];
            float x0, x1, x2, x3, x4, x5, x6, x7;
            unpack2(acc[r][0], x0, x1);
            unpack2(acc[r][1], x2, x3);
            unpack2(acc[r][2], x4, x5);
            unpack2(acc[r][3], x6, x7);
            *(float4*)(g_h + grow * RK + tc * 8)     = make_float4(x0*s, x1*s, x2*s, x3*s);
            *(float4*)(g_h + grow * RK + tc * 8 + 4) = make_float4(x4*s, x5*s, x6*s, x7*s);
        }
    }
}

// ---------------- GEMM over indexed rows (layer 1) ---------------------------
__global__ void __launch_bounds__(256, 2)
gemm_idx_kernel(const float* __restrict__ W) {
    extern __shared__ float sm[];
    float* Wsh = sm;
    float* Ash = sm + RK * RK;
    __shared__ int ridx[GEMM_BM];
    const int tid = threadIdx.x;

    {
        const float4* Wg = (const float4*)W;
        float4* Ws4 = (float4*)Wsh;
        #pragma unroll
        for (int j = 0; j < 16; j++) Ws4[tid + j * 256] = Wg[tid + j * 256];
    }

    int cnt = g_count0;
    int ntiles = (cnt + GEMM_BM - 1) / GEMM_BM;
    const int tr = tid >> 4;
    const int tc = tid & 15;

    for (int t = blockIdx.x; t < ntiles; t += gridDim.x) {
        __syncthreads();
        if (tid < GEMM_BM) {
            int gi = t * GEMM_BM + tid;
            ridx[tid] = (gi < cnt) ? g_n0_list[gi] : -1;
        }
        __syncthreads();
        #pragma unroll
        for (int j = 0; j < 8; j++) {
            int idx = tid + j * 256;
            int row = idx >> 5;
            int kq  = idx & 31;
            int gr = ridx[row];
            float4 v = make_float4(0.f, 0.f, 0.f, 0.f);
            if (gr >= 0) v = *(const float4*)(g_bufA + gr * RK + kq * 4);
            float* p = Ash + row * ASH_STRIDE + kq * 4;
            p[0] = v.x; p[1] = v.y; p[2] = v.z; p[3] = v.w;
        }
        __syncthreads();

        unsigned long long acc[4][4];
        #pragma unroll
        for (int r = 0; r < 4; r++)
            #pragma unroll
            for (int p = 0; p < 4; p++) acc[r][p] = 0ULL;

        const float* a0 = Ash + (tr * 4 + 0) * ASH_STRIDE;
        const float* a1 = Ash + (tr * 4 + 1) * ASH_STRIDE;
        const float* a2 = Ash + (tr * 4 + 2) * ASH_STRIDE;
        const float* a3 = Ash + (tr * 4 + 3) * ASH_STRIDE;
        const float* wbase = Wsh + tc * 8;

        #pragma unroll 4
        for (int k = 0; k < RK; k++) {
            ulonglong2 wA = *(const ulonglong2*)(wbase + k * RK);
            ulonglong2 wB = *(const ulonglong2*)(wbase + k * RK + 4);
            unsigned long long av0 = pack2_dup(a0[k]);
            unsigned long long av1 = pack2_dup(a1[k]);
            unsigned long long av2 = pack2_dup(a2[k]);
            unsigned long long av3 = pack2_dup(a3[k]);
            acc[0][0] = fma2(av0, wA.x, acc[0][0]);
            acc[0][1] = fma2(av0, wA.y, acc[0][1]);
            acc[0][2] = fma2(av0, wB.x, acc[0][2]);
            acc[0][3] = fma2(av0, wB.y, acc[0][3]);
            acc[1][0] = fma2(av1, wA.x, acc[1][0]);
            acc[1][1] = fma2(av1, wA.y, acc[1][1]);
            acc[1][2] = fma2(av1, wB.x, acc[1][2]);
            acc[1][3] = fma2(av1, wB.y, acc[1][3]);
            acc[2][0] = fma2(av2, wA.x, acc[2][0]);
            acc[2][1] = fma2(av2, wA.y, acc[2][1]);
            acc[2][2] = fma2(av2, wB.x, acc[2][2]);
            acc[2][3] = fma2(av2, wB.y, acc[2][3]);
            acc[3][0] = fma2(av3, wA.x, acc[3][0]);
            acc[3][1] = fma2(av3, wA.y, acc[3][1]);
            acc[3][2] = fma2(av3, wB.x, acc[3][2]);
            acc[3][3] = fma2(av3, wB.y, acc[3][3]);
        }

        #pragma unroll
        for (int r = 0; r < 4; r++) {
            int gr = ridx[tr * 4 + r];
            if (gr >= 0) {
                float s = g_inv_out[gr];
                float x0, x1, x2, x3, x4, x5, x6, x7;
                unpack2(acc[r][0], x0, x1);
                unpack2(acc[r][1], x2, x3);
                unpack2(acc[r][2], x4, x5);
                unpack2(acc[r][3], x6, x7);
                *(float4*)(g_h + gr * RK + tc * 8)     = make_float4(x0*s, x1*s, x2*s, x3*s);
                *(float4*)(g_h + gr * RK + tc * 8 + 4) = make_float4(x4*s, x5*s, x6*s, x7*s);
            }
        }
    }
}

// ---------------- aggregation + bias + LN + ReLU for one node (warp) --------
__device__ __forceinline__ void agg_node(int node, int lane, const float* b,
                                         const float* gamma, const float* beta,
                                         float* O) {
    int start = g_off[node];
    int end   = g_off[node + 1];
    const float4* H4 = (const float4*)g_h;

    float ax = 0.f, ay = 0.f, az = 0.f, aw = 0.f;
    for (int eb = start; eb < end; eb += 32) {
        int cnt = min(32, end - eb);
        int se = (lane < cnt) ? g_esrc[eb + lane] : 0;
        for (int j = 0; j < cnt; j++) {
            int s = __shfl_sync(0xffffffffu, se, j);
            float4 v = H4[s * 32 + lane];
            ax += v.x; ay += v.y; az += v.z; aw += v.w;
        }
    }

    float inv = g_inv_in[node];
    float4 bb = ((const float4*)b)[lane];
    float vx = ax * inv + bb.x;
    float vy = ay * inv + bb.y;
    float vz = az * inv + bb.z;
    float vw = aw * inv + bb.w;

    float sum = vx + vy + vz + vw;
    #pragma unroll
    for (int o = 16; o; o >>= 1) sum += __shfl_xor_sync(0xffffffffu, sum, o);
    float mean = sum * (1.0f / 128.0f);

    float cx = vx - mean, cy = vy - mean, cz = vz - mean, cw = vw - mean;
    float ss = cx * cx + cy * cy + cz * cz + cw * cw;
    #pragma unroll
    for (int o = 16; o; o >>= 1) ss += __shfl_xor_sync(0xffffffffu, ss, o);
    float rstd = rsqrtf(ss * (1.0f / 128.0f) + LN_EPS);

    float4 gm = ((const float4*)gamma)[lane];
    float4 bt = ((const float4*)beta)[lane];
    float4 o4;
    o4.x = fmaxf(cx * rstd * gm.x + bt.x, 0.f);
    o4.y = fmaxf(cy * rstd * gm.y + bt.y, 0.f);
    o4.z = fmaxf(cz * rstd * gm.z + bt.z, 0.f);
    o4.w = fmaxf(cw * rstd * gm.w + bt.w, 0.f);
    ((float4*)O)[node * 32 + lane] = o4;
}

// Indexed aggregation: level 0 -> N0 list into bufA; level 1 -> N1 list into bufB.
__global__ void __launch_bounds__(256)
agg_idx_kernel(const float* __restrict__ b, const float* __restrict__ gamma,
               const float* __restrict__ beta, int level) {
    const int* list = level ? g_n1_list : g_n0_list;
    int cnt = level ? g_count1 : g_count0;
    float* O = level ? g_bufB : g_bufA;
    int lane = threadIdx.x & 31;
    int w = (blockIdx.x * blockDim.x + threadIdx.x) >> 5;
    int nw = (gridDim.x * blockDim.x) >> 5;
    for (int i = w; i < cnt; i += nw)
        agg_node(list[i], lane, b, gamma, beta, O);
}

// ---------------- final layer: per-target matvec + agg + LN -----------------
#define FINAL_SMEM_BYTES ((RK * RK + RK) * 4)
__global__ void __launch_bounds__(128)
final_kernel(const float* __restrict__ W, const float* __restrict__ b,
             const float* __restrict__ gamma, const float* __restrict__ beta,
             float* __restrict__ out) {
    extern __shared__ float sm[];
    float* Wsh = sm;            // 128x128
    float* xs  = sm + RK * RK;  // 128
    __shared__ float red[8];
    int t = threadIdx.x;
    int lane = t & 31, wid = t >> 5;

    {
        const float4* Wg = (const float4*)W;
        float4* Ws4 = (float4*)Wsh;
        #pragma unroll
        for (int j = 0; j < 32; j++) Ws4[t + j * 128] = Wg[t + j * 128];
    }

    int node = g_tgt[blockIdx.x];
    int st = g_off[node], en = g_off[node + 1];
    float acc = 0.f;
    for (int e = st; e < en; e++) {
        int s = g_esrc[e];
        __syncthreads();
        xs[t] = g_bufB[s * RK + t] * g_inv_out[s];
        __syncthreads();
        float y = 0.f;
        #pragma unroll 16
        for (int k = 0; k < RK; k++) y += xs[k] * Wsh[k * RK + t];
        acc += y;
    }

    float v = acc * g_inv_in[node] + b[t];

    float sum = v;
    #pragma unroll
    for (int o = 16; o; o >>= 1) sum += __shfl_xor_sync(0xffffffffu, sum, o);
    if (lane == 0) red[wid] = sum;
    __syncthreads();
    float mean = (red[0] + red[1] + red[2] + red[3]) * (1.0f / 128.0f);

    float c = v - mean;
    float ss = c * c;
    #pragma unroll
    for (int o = 16; o; o >>= 1) ss += __shfl_xor_sync(0xffffffffu, ss, o);
    if (lane == 0) red[4 + wid] = ss;
    __syncthreads();
    float rstd = rsqrtf((red[4] + red[5] + red[6] + red[7]) * (1.0f / 128.0f) + LN_EPS);

    out[blockIdx.x * RK + t] = fmaxf(c * rstd * gamma[t] + beta[t], 0.f);
}

// ---------------- launch ----------------------------------------------------
extern "C" void kernel_launch(void* const* d_in, const int* in_sizes, int n_in,
                              void* d_out, int out_size) {
    const float* features = (const float*)d_in[0];
    const int*   src      = (const int*)d_in[1];
    const int*   dst      = (const int*)d_in[2];
    const int*   bnn      = (const int*)d_in[3];
    const float* Ws       = (const float*)d_in[4];
    const float* bs       = (const float*)d_in[5];
    const float* gammas   = (const float*)d_in[6];
    const float* betas    = (const float*)d_in[7];
    float* out = (float*)d_out;

    cudaFuncSetAttribute(gemm_full_kernel, cudaFuncAttributeMaxDynamicSharedMemorySize,
                         GEMM_SMEM_BYTES);
    cudaFuncSetAttribute(gemm_idx_kernel, cudaFuncAttributeMaxDynamicSharedMemorySize,
                         GEMM_SMEM_BYTES);
    cudaFuncSetAttribute(final_kernel, cudaFuncAttributeMaxDynamicSharedMemorySize,
                         FINAL_SMEM_BYTES);

    zero_kernel<<<(NN + 255) / 256, 256>>>();
    degree_kernel<<<(NE + 255) / 256, 256>>>(src, dst);
    invsqrt_kernel<<<(NN + 255) / 256, 256>>>();
    scan1_kernel<<<NB, 1024>>>();
    scan2_kernel<<<1, 64>>>();
    scan3_kernel<<<NB, 1024>>>();
    bucket_fill_kernel<<<(NE + 255) / 256, 256>>>(src, dst);
    frontier1_kernel<<<1, 256>>>(bnn);
    frontier0_kernel<<<64, 256>>>();

    // Layer 0: full GEMM, aggregation only at N0
    gemm_full_kernel<<<(NN + GEMM_BM - 1) / GEMM_BM, 256, GEMM_SMEM_BYTES>>>(features, Ws);
    agg_idx_kernel<<<256, 256>>>(bs, gammas, betas, 0);

    // Layer 1: GEMM over N0 rows only, aggregation only at N1
    gemm_idx_kernel<<<120, 256, GEMM_SMEM_BYTES>>>(Ws + RK * RK);
    agg_idx_kernel<<<64, 256>>>(bs + RK, gammas + RK, betas + RK, 1);

    // Layer 2: fused per-target matvec + aggregation + LN + ReLU
    final_kernel<<<NG, 128, FINAL_SMEM_BYTES>>>(Ws + 2 * RK * RK, bs + 2 * RK,
                                                gammas + 2 * RK, betas + 2 * RK, out);
}

// round 4
// speedup vs baseline: 2.7768x; 1.4106x over previous
#include <cuda_runtime.h>
#include <cuda_bf16.h>

#define NN 50000
#define NE 640000
#define RK 128
#define NG 50
#define LN_EPS 1e-5f
#define NB 49   // ceil(50000/1024)

// ---------------- zero-initialized prep block (single memset) ---------------
struct PrepZero {
    int deg_in[NN];
    int deg_out[NN];
    int need[NN];    // CSR needed at this dst (targets ∪ N1 ∪ N0)
    int mark0[NN];
    int mark1[NN];
    int mtgt[NN];
    int count0;
    int count1;
};
__device__ PrepZero g_z;

// ---------------- other scratch ---------------------------------------------
__device__ float g_h[NN * RK];      // post-GEMM features (UNscaled)
__device__ float g_bufA[NN * RK];   // feats1 (valid at N0 rows)
__device__ float g_bufB[NN * RK];   // feats2 (valid at N1 rows)
__device__ float g_inv_in[NN];
__device__ float g_inv_out[NN];
__device__ int   g_off[NN + 1];
__device__ int   g_cur[NN];
__device__ int   g_esrc[NE];
__device__ int   g_bsum[64];
__device__ int   g_tgt[NG];
__device__ int   g_n0_list[NN];
__device__ int   g_n1_list[NN];

// ---------------- f32x2 helpers ---------------------------------------------
__device__ __forceinline__ unsigned long long pack2_dup(float x) {
    unsigned long long r;
    unsigned int u = __float_as_uint(x);
    asm("mov.b64 %0, {%1, %1};" : "=l"(r) : "r"(u));
    return r;
}
__device__ __forceinline__ unsigned long long fma2(unsigned long long a,
                                                   unsigned long long b,
                                                   unsigned long long c) {
    unsigned long long d;
    asm("fma.rn.f32x2 %0, %1, %2, %3;" : "=l"(d) : "l"(a), "l"(b), "l"(c));
    return d;
}
__device__ __forceinline__ void unpack2(unsigned long long v, float& a, float& b) {
    unsigned int lo, hi;
    asm("mov.b64 {%0, %1}, %2;" : "=r"(lo), "=r"(hi) : "l"(v));
    a = __uint_as_float(lo);
    b = __uint_as_float(hi);
}

// ---------------- prep: targets + frontier via edge scans -------------------
__global__ void tgt_init_kernel(const int* __restrict__ bnn) {
    __shared__ int sb[NG];
    int t = threadIdx.x;
    if (t < NG) sb[t] = bnn[t];
    __syncthreads();
    if (t == 0) {
        int base = 0;
        for (int i = 0; i < NG; i++) {
            g_tgt[i] = base;
            g_z.mtgt[base] = 1;
            g_z.need[base] = 1;
            base += sb[i];
        }
    }
}

__global__ void p_n1_kernel(const int* __restrict__ src, const int* __restrict__ dst) {
    int i = blockIdx.x * blockDim.x + threadIdx.x;
    if (i < NE) {
        int d = dst[i];
        if (g_z.mtgt[d]) {
            int s = src[i];
            if (atomicExch(&g_z.mark1[s], 1) == 0) {
                int p = atomicAdd(&g_z.count1, 1);
                g_n1_list[p] = s;
            }
            g_z.need[s] = 1;
        }
    }
}

__global__ void p_n0_kernel(const int* __restrict__ src, const int* __restrict__ dst) {
    int i = blockIdx.x * blockDim.x + threadIdx.x;
    if (i < NE) {
        int d = dst[i];
        if (g_z.mark1[d]) {
            int s = src[i];
            if (atomicExch(&g_z.mark0[s], 1) == 0) {
                int p = atomicAdd(&g_z.count0, 1);
                g_n0_list[p] = s;
            }
            g_z.need[s] = 1;
        }
    }
}

__global__ void p_deg_kernel(const int* __restrict__ src, const int* __restrict__ dst) {
    int i = blockIdx.x * blockDim.x + threadIdx.x;
    if (i < NE) {
        atomicAdd(&g_z.deg_out[src[i]], 1);
        int d = dst[i];
        if (g_z.need[d]) atomicAdd(&g_z.deg_in[d], 1);
    }
}

// scan pass 1: block-local exclusive scan of deg_in; also compute inv factors.
__global__ void scan1_kernel() {
    __shared__ int wsum[32];
    int tid = threadIdx.x, lane = tid & 31, wid = tid >> 5;
    int i = blockIdx.x * 1024 + tid;
    int v = (i < NN) ? g_z.deg_in[i] : 0;
    if (i < NN) {
        g_inv_in[i]  = rsqrtf(fmaxf((float)v, 1.0f));
        g_inv_out[i] = rsqrtf(fmaxf((float)g_z.deg_out[i], 1.0f));
    }
    int x = v;
    #pragma unroll
    for (int o = 1; o < 32; o <<= 1) {
        int t = __shfl_up_sync(0xffffffffu, x, o);
        if (lane >= o) x += t;
    }
    if (lane == 31) wsum[wid] = x;
    __syncthreads();
    if (wid == 0) {
        int y = wsum[lane];
        #pragma unroll
        for (int o = 1; o < 32; o <<= 1) {
            int t = __shfl_up_sync(0xffffffffu, y, o);
            if (lane >= o) y += t;
        }
        wsum[lane] = y;
    }
    __syncthreads();
    int wpref = wid ? wsum[wid - 1] : 0;
    int incl = x + wpref;
    if (i < NN) g_off[i] = incl - v;
    if (tid == 1023) g_bsum[blockIdx.x] = incl;
}

// scan pass 2+3 fused: every block redundantly scans bsums, then offsets.
__global__ void scan23_kernel() {
    __shared__ int sb[64];
    __shared__ int spref, stot;
    int tid = threadIdx.x;
    if (tid < 64) sb[tid] = (tid < NB) ? g_bsum[tid] : 0;
    __syncthreads();
    if (tid == 0) {
        int tot = 0;
        for (int i = 0; i < NB; i++) { int t = sb[i]; sb[i] = tot; tot += t; }
        spref = sb[blockIdx.x];
        stot = tot;
    }
    __syncthreads();
    int i = blockIdx.x * 1024 + tid;
    if (i < NN) {
        int o = g_off[i] + spref;
        g_off[i] = o;
        g_cur[i] = o;
    }
    if (blockIdx.x == 0 && tid == 0) g_off[NN] = stot;
}

__global__ void p_fill_kernel(const int* __restrict__ src, const int* __restrict__ dst) {
    int i = blockIdx.x * blockDim.x + threadIdx.x;
    if (i < NE) {
        int d = dst[i];
        if (g_z.need[d]) {
            int p = atomicAdd(&g_cur[d], 1);
            g_esrc[p] = src[i];
        }
    }
}

// ---------------- GEMM0: persistent, g_h = X @ W (unscaled) ------------------
// 256 threads, 64-row tiles. Warp w: rows w*8..w*8+7 (A broadcast from dup'd
// smem), lane: cols lane*4..lane*4+3. W LDS traffic = 0.5 B/MAC.
#define GF_TILE 64
#define GF_SMEM (RK * RK * 4 + GF_TILE * RK * 8)  // W 64KB + dup'd A 64KB

__global__ void __launch_bounds__(256, 1)
gemm0_kernel(const float* __restrict__ X, const float* __restrict__ W) {
    extern __shared__ float sm[];
    float* Wsh = sm;                              // 128x128 floats
    float2* Ad = (float2*)(sm + RK * RK);         // 64 x 128 float2 (dup)
    const int tid = threadIdx.x;
    const int lane = tid & 31;
    const int wid = tid >> 5;

    {
        const float4* Wg = (const float4*)W;
        float4* Ws4 = (float4*)Wsh;
        #pragma unroll
        for (int j = 0; j < 16; j++) Ws4[tid + j * 256] = Wg[tid + j * 256];
    }

    const int ntiles = (NN + GF_TILE - 1) / GF_TILE;
    const int myrow = tid >> 5;          // load phase: warp -> rows {w, w+8, ...}
    const int kq = tid & 31;

    // preload first tile into registers
    float4 pre[8];
    {
        int t0 = blockIdx.x;
        int rowBase = t0 * GF_TILE;
        #pragma unroll
        for (int j = 0; j < 8; j++) {
            int grow = rowBase + myrow + j * 8;
            pre[j] = make_float4(0.f, 0.f, 0.f, 0.f);
            if (t0 < ntiles && grow < NN)
                pre[j] = *(const float4*)(X + grow * RK + kq * 4);
        }
    }

    for (int t = blockIdx.x; t < ntiles; t += gridDim.x) {
        __syncthreads();   // Ad no longer read by previous iteration
        // store dup'd A tile
        #pragma unroll
        for (int j = 0; j < 8; j++) {
            float4 v = pre[j];
            float4* p4 = (float4*)(Ad + (myrow + j * 8) * RK + kq * 4);
            p4[0] = make_float4(v.x, v.x, v.y, v.y);
            p4[1] = make_float4(v.z, v.z, v.w, v.w);
        }
        __syncthreads();

        // prefetch next tile
        {
            int tn = t + gridDim.x;
            int rowBase = tn * GF_TILE;
            #pragma unroll
            for (int j = 0; j < 8; j++) {
                int grow = rowBase + myrow + j * 8;
                pre[j] = make_float4(0.f, 0.f, 0.f, 0.f);
                if (tn < ntiles && grow < NN)
                    pre[j] = *(const float4*)(X + grow * RK + kq * 4);
            }
        }

        unsigned long long acc[8][2];
        #pragma unroll
        for (int r = 0; r < 8; r++) { acc[r][0] = 0ULL; acc[r][1] = 0ULL; }

        const unsigned long long* Adu =
            (const unsigned long long*)(Ad + (wid * 8) * RK);

        #pragma unroll 4
        for (int k = 0; k < RK; k++) {
            ulonglong2 wv = *(const ulonglong2*)(Wsh + k * RK + lane * 4);
            #pragma unroll
            for (int r = 0; r < 8; r++) {
                unsigned long long av = Adu[r * RK + k];
                acc[r][0] = fma2(av, wv.x, acc[r][0]);
                acc[r][1] = fma2(av, wv.y, acc[r][1]);
            }
        }

        int rowBase = t * GF_TILE;
        #pragma unroll
        for (int r = 0; r < 8; r++) {
            int grow = rowBase + wid * 8 + r;
            if (grow < NN) {
                float x0, x1, x2, x3;
                unpack2(acc[r][0], x0, x1);
                unpack2(acc[r][1], x2, x3);
                *(float4*)(g_h + grow * RK + lane * 4) = make_float4(x0, x1, x2, x3);
            }
        }
    }
}

// ---------------- GEMM over indexed rows (layer 1), unscaled output ---------
#define GEMM_BM 64
#define ASH_STRIDE 129
#define GEMM_SMEM_BYTES ((RK * RK + GEMM_BM * ASH_STRIDE) * 4)

__global__ void __launch_bounds__(256, 2)
gemm_idx_kernel(const float* __restrict__ W) {
    extern __shared__ float sm[];
    float* Wsh = sm;
    float* Ash = sm + RK * RK;
    __shared__ int ridx[GEMM_BM];
    const int tid = threadIdx.x;

    {
        const float4* Wg = (const float4*)W;
        float4* Ws4 = (float4*)Wsh;
        #pragma unroll
        for (int j = 0; j < 16; j++) Ws4[tid + j * 256] = Wg[tid + j * 256];
    }

    int cnt = g_z.count0;
    int ntiles = (cnt + GEMM_BM - 1) / GEMM_BM;
    const int tr = tid >> 4;
    const int tc = tid & 15;

    for (int t = blockIdx.x; t < ntiles; t += gridDim.x) {
        __syncthreads();
        if (tid < GEMM_BM) {
            int gi = t * GEMM_BM + tid;
            ridx[tid] = (gi < cnt) ? g_n0_list[gi] : -1;
        }
        __syncthreads();
        #pragma unroll
        for (int j = 0; j < 8; j++) {
            int idx = tid + j * 256;
            int row = idx >> 5;
            int kq  = idx & 31;
            int gr = ridx[row];
            float4 v = make_float4(0.f, 0.f, 0.f, 0.f);
            if (gr >= 0) v = *(const float4*)(g_bufA + gr * RK + kq * 4);
            float* p = Ash + row * ASH_STRIDE + kq * 4;
            p[0] = v.x; p[1] = v.y; p[2] = v.z; p[3] = v.w;
        }
        __syncthreads();

        unsigned long long acc[4][4];
        #pragma unroll
        for (int r = 0; r < 4; r++)
            #pragma unroll
            for (int p = 0; p < 4; p++) acc[r][p] = 0ULL;

        const float* a0 = Ash + (tr * 4 + 0) * ASH_STRIDE;
        const float* a1 = Ash + (tr * 4 + 1) * ASH_STRIDE;
        const float* a2 = Ash + (tr * 4 + 2) * ASH_STRIDE;
        const float* a3 = Ash + (tr * 4 + 3) * ASH_STRIDE;
        const float* wbase = Wsh + tc * 8;

        #pragma unroll 4
        for (int k = 0; k < RK; k++) {
            ulonglong2 wA = *(const ulonglong2*)(wbase + k * RK);
            ulonglong2 wB = *(const ulonglong2*)(wbase + k * RK + 4);
            unsigned long long av0 = pack2_dup(a0[k]);
            unsigned long long av1 = pack2_dup(a1[k]);
            unsigned long long av2 = pack2_dup(a2[k]);
            unsigned long long av3 = pack2_dup(a3[k]);
            acc[0][0] = fma2(av0, wA.x, acc[0][0]);
            acc[0][1] = fma2(av0, wA.y, acc[0][1]);
            acc[0][2] = fma2(av0, wB.x, acc[0][2]);
            acc[0][3] = fma2(av0, wB.y, acc[0][3]);
            acc[1][0] = fma2(av1, wA.x, acc[1][0]);
            acc[1][1] = fma2(av1, wA.y, acc[1][1]);
            acc[1][2] = fma2(av1, wB.x, acc[1][2]);
            acc[1][3] = fma2(av1, wB.y, acc[1][3]);
            acc[2][0] = fma2(av2, wA.x, acc[2][0]);
            acc[2][1] = fma2(av2, wA.y, acc[2][1]);
            acc[2][2] = fma2(av2, wB.x, acc[2][2]);
            acc[2][3] = fma2(av2, wB.y, acc[2][3]);
            acc[3][0] = fma2(av3, wA.x, acc[3][0]);
            acc[3][1] = fma2(av3, wA.y, acc[3][1]);
            acc[3][2] = fma2(av3, wB.x, acc[3][2]);
            acc[3][3] = fma2(av3, wB.y, acc[3][3]);
        }

        #pragma unroll
        for (int r = 0; r < 4; r++) {
            int gr = ridx[tr * 4 + r];
            if (gr >= 0) {
                float x0, x1, x2, x3, x4, x5, x6, x7;
                unpack2(acc[r][0], x0, x1);
                unpack2(acc[r][1], x2, x3);
                unpack2(acc[r][2], x4, x5);
                unpack2(acc[r][3], x6, x7);
                *(float4*)(g_h + gr * RK + tc * 8)     = make_float4(x0, x1, x2, x3);
                *(float4*)(g_h + gr * RK + tc * 8 + 4) = make_float4(x4, x5, x6, x7);
            }
        }
    }
}

// ---------------- aggregation (inv_out applied at read) + LN + ReLU ---------
__device__ __forceinline__ void agg_node(int node, int lane, const float* b,
                                         const float* gamma, const float* beta,
                                         float* O) {
    int start = g_off[node];
    int end   = g_off[node + 1];
    const float4* H4 = (const float4*)g_h;

    float ax = 0.f, ay = 0.f, az = 0.f, aw = 0.f;
    for (int eb = start; eb < end; eb += 32) {
        int cnt = min(32, end - eb);
        int se = 0;
        float iov = 0.f;
        if (lane < cnt) {
            se = g_esrc[eb + lane];
            iov = g_inv_out[se];
        }
        for (int j = 0; j < cnt; j++) {
            int s = __shfl_sync(0xffffffffu, se, j);
            float io = __shfl_sync(0xffffffffu, iov, j);
            float4 v = H4[s * 32 + lane];
            ax = fmaf(v.x, io, ax);
            ay = fmaf(v.y, io, ay);
            az = fmaf(v.z, io, az);
            aw = fmaf(v.w, io, aw);
        }
    }

    float inv = g_inv_in[node];
    float4 bb = ((const float4*)b)[lane];
    float vx = ax * inv + bb.x;
    float vy = ay * inv + bb.y;
    float vz = az * inv + bb.z;
    float vw = aw * inv + bb.w;

    float sum = vx + vy + vz + vw;
    #pragma unroll
    for (int o = 16; o; o >>= 1) sum += __shfl_xor_sync(0xffffffffu, sum, o);
    float mean = sum * (1.0f / 128.0f);

    float cx = vx - mean, cy = vy - mean, cz = vz - mean, cw = vw - mean;
    float ss = cx * cx + cy * cy + cz * cz + cw * cw;
    #pragma unroll
    for (int o = 16; o; o >>= 1) ss += __shfl_xor_sync(0xffffffffu, ss, o);
    float rstd = rsqrtf(ss * (1.0f / 128.0f) + LN_EPS);

    float4 gm = ((const float4*)gamma)[lane];
    float4 bt = ((const float4*)beta)[lane];
    float4 o4;
    o4.x = fmaxf(cx * rstd * gm.x + bt.x, 0.f);
    o4.y = fmaxf(cy * rstd * gm.y + bt.y, 0.f);
    o4.z = fmaxf(cz * rstd * gm.z + bt.z, 0.f);
    o4.w = fmaxf(cw * rstd * gm.w + bt.w, 0.f);
    ((float4*)O)[node * 32 + lane] = o4;
}

__global__ void __launch_bounds__(256)
agg_idx_kernel(const float* __restrict__ b, const float* __restrict__ gamma,
               const float* __restrict__ beta, int level) {
    const int* list = level ? g_n1_list : g_n0_list;
    int cnt = level ? g_z.count1 : g_z.count0;
    float* O = level ? g_bufB : g_bufA;
    int lane = threadIdx.x & 31;
    int w = (blockIdx.x * blockDim.x + threadIdx.x) >> 5;
    int nw = (gridDim.x * blockDim.x) >> 5;
    for (int i = w; i < cnt; i += nw)
        agg_node(list[i], lane, b, gamma, beta, O);
}

// ---------------- final layer: per-target matvec + agg + LN -----------------
#define FINAL_SMEM_BYTES ((RK * RK + RK) * 4)
__global__ void __launch_bounds__(128)
final_kernel(const float* __restrict__ W, const float* __restrict__ b,
             const float* __restrict__ gamma, const float* __restrict__ beta,
             float* __restrict__ out) {
    extern __shared__ float sm[];
    float* Wsh = sm;
    float* xs  = sm + RK * RK;
    __shared__ float red[8];
    int t = threadIdx.x;
    int lane = t & 31, wid = t >> 5;

    {
        const float4* Wg = (const float4*)W;
        float4* Ws4 = (float4*)Wsh;
        #pragma unroll
        for (int j = 0; j < 32; j++) Ws4[t + j * 128] = Wg[t + j * 128];
    }

    int node = g_tgt[blockIdx.x];
    int st = g_off[node], en = g_off[node + 1];
    float acc = 0.f;
    for (int e = st; e < en; e++) {
        int s = g_esrc[e];
        __syncthreads();
        xs[t] = g_bufB[s * RK + t] * g_inv_out[s];
        __syncthreads();
        float y = 0.f;
        #pragma unroll 16
        for (int k = 0; k < RK; k++) y += xs[k] * Wsh[k * RK + t];
        acc += y;
    }

    float v = acc * g_inv_in[node] + b[t];

    float sum = v;
    #pragma unroll
    for (int o = 16; o; o >>= 1) sum += __shfl_xor_sync(0xffffffffu, sum, o);
    if (lane == 0) red[wid] = sum;
    __syncthreads();
    float mean = (red[0] + red[1] + red[2] + red[3]) * (1.0f / 128.0f);

    float c = v - mean;
    float ss = c * c;
    #pragma unroll
    for (int o = 16; o; o >>= 1) ss += __shfl_xor_sync(0xffffffffu, ss, o);
    if (lane == 0) red[4 + wid] = ss;
    __syncthreads();
    float rstd = rsqrtf((red[4] + red[5] + red[6] + red[7]) * (1.0f / 128.0f) + LN_EPS);

    out[blockIdx.x * RK + t] = fmaxf(c * rstd * gamma[t] + beta[t], 0.f);
}

// ---------------- launch ----------------------------------------------------
extern "C" void kernel_launch(void* const* d_in, const int* in_sizes, int n_in,
                              void* d_out, int out_size) {
    const float* features = (const float*)d_in[0];
    const int*   src      = (const int*)d_in[1];
    const int*   dst      = (const int*)d_in[2];
    const int*   bnn      = (const int*)d_in[3];
    const float* Ws       = (const float*)d_in[4];
    const float* bs       = (const float*)d_in[5];
    const float* gammas   = (const float*)d_in[6];
    const float* betas    = (const float*)d_in[7];
    float* out = (float*)d_out;

    static cudaStream_t s_side = nullptr;
    static cudaEvent_t e_fork = nullptr, e_join = nullptr;
    if (!s_side) {
        cudaStreamCreateWithFlags(&s_side, cudaStreamNonBlocking);
        cudaEventCreateWithFlags(&e_fork, cudaEventDisableTiming);
        cudaEventCreateWithFlags(&e_join, cudaEventDisableTiming);
    }

    cudaFuncSetAttribute(gemm0_kernel, cudaFuncAttributeMaxDynamicSharedMemorySize,
                         GF_SMEM);
    cudaFuncSetAttribute(gemm_idx_kernel, cudaFuncAttributeMaxDynamicSharedMemorySize,
                         GEMM_SMEM_BYTES);
    cudaFuncSetAttribute(final_kernel, cudaFuncAttributeMaxDynamicSharedMemorySize,
                         FINAL_SMEM_BYTES);

    // --- side stream: layer-0 GEMM (independent of all graph prep) ----------
    cudaEventRecord(e_fork, 0);
    cudaStreamWaitEvent(s_side, e_fork, 0);
    gemm0_kernel<<<148, 256, GF_SMEM, s_side>>>(features, Ws);
    cudaEventRecord(e_join, s_side);

    // --- main stream: graph prep --------------------------------------------
    void* zp = nullptr;
    cudaGetSymbolAddress(&zp, g_z);
    cudaMemsetAsync(zp, 0, sizeof(PrepZero), 0);

    tgt_init_kernel<<<1, 64>>>(bnn);
    p_n1_kernel<<<(NE + 255) / 256, 256>>>(src, dst);
    p_n0_kernel<<<(NE + 255) / 256, 256>>>(src, dst);
    p_deg_kernel<<<(NE + 255) / 256, 256>>>(src, dst);
    scan1_kernel<<<NB, 1024>>>();
    scan23_kernel<<<NB, 1024>>>();
    p_fill_kernel<<<(NE + 255) / 256, 256>>>(src, dst);

    // --- join: aggregation needs g_h from gemm0 ------------------------------
    cudaStreamWaitEvent(0, e_join, 0);

    agg_idx_kernel<<<256, 256>>>(bs, gammas, betas, 0);
    gemm_idx_kernel<<<120, 256, GEMM_SMEM_BYTES>>>(Ws + RK * RK);
    agg_idx_kernel<<<64, 256>>>(bs + RK, gammas + RK, betas + RK, 1);
    final_kernel<<<NG, 128, FINAL_SMEM_BYTES>>>(Ws + 2 * RK * RK, bs + 2 * RK,
                                                gammas + 2 * RK, betas + 2 * RK, out);
}